// round 11
// baseline (speedup 1.0000x reference)
#include <cuda_runtime.h>
#include <cstdint>

#define HIDDEN  4096
#define RANK    16
#define ROWS    4
#define THREADS 256
#define NWARP   8
#define TOTAL_ROWS 16384
#define TWO_OVER_PI 0.63661977236758134f

// Dequantized weights in device scratch (no allocations).
// g_Aft[r*HIDDEN+k] = A[k][r] * sA[r] * 2/pi   (transposed, coalesced loads)
// g_Bf [r*HIDDEN+c] = B[r][c] * sB[c]
__device__ float g_Aft[RANK * HIDDEN];
__device__ float g_Bf[RANK * HIDDEN];

// --- storage-format probe (validated R4+) ---
__device__ __forceinline__ int detect_mode(const void* p) {
    const unsigned* w = (const unsigned*)p;
    int vi = 0, vf = 0;
    #pragma unroll
    for (int i = 0; i < 32; i++) {
        unsigned u = w[i];
        int s = (int)u;
        if (s >= -127 && s <= 127) vi++;
        unsigned exp = (u >> 23) & 0xffu;
        if ((u & 0x7fffffffu) == 0u || (exp >= 127u && exp <= 133u)) vf++;
    }
    if (vi >= 24) return 1;
    if (vf >= 24) return 0;
    return 2;
}
__device__ __forceinline__ float load_elem(const void* p, int mode, int i) {
    if (mode == 1) return (float)((const int*)p)[i];
    if (mode == 0) return ((const float*)p)[i];
    return (float)((const signed char*)p)[i];
}

__global__ void prep_kernel(const void* __restrict__ A, const void* __restrict__ B,
                            const float* __restrict__ sA, const float* __restrict__ sB)
{
    __shared__ int mA, mB;
    if (threadIdx.x == 0) { mA = detect_mode(A); mB = detect_mode(B); }
    __syncthreads();
    const int i = blockIdx.x * blockDim.x + threadIdx.x;    // 65536 threads
    {
        const int k = i >> 4, r = i & 15;
        g_Aft[(size_t)r * HIDDEN + k] = load_elem(A, mA, i) * sA[r] * TWO_OVER_PI;
    }
    g_Bf[i] = load_elem(B, mB, i) * sB[i & (HIDDEN - 1)];
}

// sin(t): exact identity sin(t) = (-1)^q sin(t - q*pi); Cody-Waite 2-term pi;
// degree-9 odd minimax polynomial on |r| <= pi/2 (FMA pipe only).
__device__ __forceinline__ float fast_sin(float t) {
    const int qi = __float2int_rn(t * 0.3183098861837907f);
    const float q = (float)qi;
    float r = fmaf(q, -3.14159274101257f, t);
    r = fmaf(q, 8.742277657e-8f, r);
    r = (qi & 1) ? -r : r;
    const float s = r * r;
    float p = 2.86567956e-6f;
    p = fmaf(p, s, -1.98559923e-4f);
    p = fmaf(p, s,  8.33338592e-3f);
    p = fmaf(p, s, -1.66666672e-1f);
    return fmaf(p, r * s, r);
}

__global__ __launch_bounds__(THREADS, 3)          // 3 CTAs/SM: 24 warps (was 16)
void pilora_kernel(const float* __restrict__ x, float* __restrict__ y)
{
    extern __shared__ float xs[];                 // [ROWS][HIDDEN]  64 KB
    __shared__ float red[NWARP][ROWS * (RANK / 2)];   // per-warp partials, half-rank
    __shared__ float hs[ROWS * RANK];

    const int tid  = threadIdx.x;
    const int lane = tid & 31;
    const int w    = tid >> 5;
    const size_t rowbase = (size_t)blockIdx.x * ROWS;

    // ---- stage x tile (coalesced float4) ----
    {
        const float4* xg4 = (const float4*)(x + rowbase * HIDDEN);
        float4* xs4 = (float4*)xs;
        #pragma unroll
        for (int i = 0; i < (ROWS * HIDDEN / 4) / THREADS; i++)
            xs4[tid + i * THREADS] = xg4[tid + i * THREADS];
    }
    __syncthreads();

    // ---- phase 1: two rank-half passes, acc[4][8] (32 regs instead of 64) ----
    #pragma unroll
    for (int half = 0; half < 2; half++) {
        float acc[ROWS][RANK / 2];
        #pragma unroll
        for (int rr = 0; rr < ROWS; rr++)
            #pragma unroll
            for (int r = 0; r < RANK / 2; r++)
                acc[rr][r] = 0.0f;

        #pragma unroll
        for (int i = 0; i < 4; i++) {
            const int k0 = w * 512 + i * 128 + lane * 4;

            float4 xv[ROWS];
            #pragma unroll
            for (int rr = 0; rr < ROWS; rr++)
                xv[rr] = *(const float4*)(xs + rr * HIDDEN + k0);

            #pragma unroll
            for (int r = 0; r < RANK / 2; r++) {
                const float4 av =
                    *(const float4*)(g_Aft + (size_t)(half * 8 + r) * HIDDEN + k0);
                #pragma unroll
                for (int rr = 0; rr < ROWS; rr++) {
                    float t = acc[rr][r];
                    t = fmaf(xv[rr].x, av.x, t);
                    t = fmaf(xv[rr].y, av.y, t);
                    t = fmaf(xv[rr].z, av.z, t);
                    t = fmaf(xv[rr].w, av.w, t);
                    acc[rr][r] = t;
                }
            }
        }

        // warp butterfly reduction; lane 0 stores per-warp partials
        #pragma unroll
        for (int rr = 0; rr < ROWS; rr++) {
            #pragma unroll
            for (int r = 0; r < RANK / 2; r++) {
                float v = acc[rr][r];
                v += __shfl_xor_sync(0xffffffffu, v, 16);
                v += __shfl_xor_sync(0xffffffffu, v, 8);
                v += __shfl_xor_sync(0xffffffffu, v, 4);
                v += __shfl_xor_sync(0xffffffffu, v, 2);
                v += __shfl_xor_sync(0xffffffffu, v, 1);
                if (lane == 0) red[w][rr * (RANK / 2) + r] = v;
            }
        }
        __syncthreads();

        if (tid < ROWS * (RANK / 2)) {
            float h = 0.0f;
            #pragma unroll
            for (int ww = 0; ww < NWARP; ww++) h += red[ww][tid];
            const int rr = tid / (RANK / 2);
            const int r  = tid % (RANK / 2);
            hs[rr * RANK + half * 8 + r] = h;     // sA, 2/pi folded into Aft
        }
        __syncthreads();                           // red reused next half
    }

    // ---- phase 2: y = x + 2*sin( sum_r hs[row][r] * Bf[r][c] ) ----
    // hs read as smem broadcasts (R9 proved hoisting them is perf-neutral;
    // keeping them in smem saves 64 registers -> enables 3 CTAs/SM).
    #pragma unroll
    for (int i = 0; i < 4; i++) {
        const int c0 = w * 512 + i * 128 + lane * 4;

        float acc2[ROWS][4];
        #pragma unroll
        for (int rr = 0; rr < ROWS; rr++)
            #pragma unroll
            for (int j = 0; j < 4; j++)
                acc2[rr][j] = 0.0f;

        #pragma unroll
        for (int r = 0; r < RANK; r++) {
            const float4 bv = *(const float4*)(g_Bf + (size_t)r * HIDDEN + c0);
            const float b[4] = {bv.x, bv.y, bv.z, bv.w};
            #pragma unroll
            for (int rr = 0; rr < ROWS; rr++) {
                const float hr = hs[rr * RANK + r];   // conflict-free broadcast
                #pragma unroll
                for (int j = 0; j < 4; j++)
                    acc2[rr][j] = fmaf(hr, b[j], acc2[rr][j]);
            }
        }

        #pragma unroll
        for (int rr = 0; rr < ROWS; rr++) {
            const float4 xv = *(const float4*)(xs + rr * HIDDEN + c0);
            float4 ov;
            ov.x = fmaf(2.0f, fast_sin(acc2[rr][0]), xv.x);
            ov.y = fmaf(2.0f, fast_sin(acc2[rr][1]), xv.y);
            ov.z = fmaf(2.0f, fast_sin(acc2[rr][2]), xv.z);
            ov.w = fmaf(2.0f, fast_sin(acc2[rr][3]), xv.w);
            *(float4*)(y + (rowbase + rr) * HIDDEN + c0) = ov;
        }
    }
}

extern "C" void kernel_launch(void* const* d_in, const int* in_sizes, int n_in,
                              void* d_out, int out_size)
{
    // Rank-order binding by size (robust; validated since R4)
    int idx[16];
    const int m = (n_in < 16) ? n_in : 16;
    for (int i = 0; i < m; i++) idx[i] = i;
    for (int i = 0; i < m; i++) {
        int best = i;
        for (int j = i + 1; j < m; j++)
            if (in_sizes[idx[j]] < in_sizes[idx[best]]) best = j;
        if (best != i) {
            int t = idx[best];
            for (int j = best; j > i; j--) idx[j] = idx[j - 1];
            idx[i] = t;
        }
    }
    const float* sA = (const float*)d_in[idx[0]];
    const float* sB = (const float*)d_in[idx[1]];
    const void*  A  = d_in[idx[2]];
    const void*  B  = d_in[idx[3]];
    const float* x  = (const float*)d_in[idx[m - 1]];
    float* y = (float*)d_out;

    prep_kernel<<<(HIDDEN * RANK) / 256, 256>>>(A, B, sA, sB);

    const size_t smem = (size_t)ROWS * HIDDEN * sizeof(float);   // 64 KB
    cudaFuncSetAttribute(pilora_kernel,
                         cudaFuncAttributeMaxDynamicSharedMemorySize, (int)smem);
    pilora_kernel<<<TOTAL_ROWS / ROWS, THREADS, smem>>>(x, y);
}

// round 12
// speedup vs baseline: 1.0287x; 1.0287x over previous
#include <cuda_runtime.h>
#include <cuda_bf16.h>
#include <cstdint>

#define HIDDEN  4096
#define RANK    16
#define ROWS    4
#define THREADS 256
#define NWARP   8
#define TOTAL_ROWS 16384
#define TWO_OVER_PI 0.63661977236758134f

// Weights stored as bf16 holding EXACT int8 integer values (no scale folded:
// int8 in [-127,127] is exactly representable in bf16; scales applied in fp32
// later, so the whole pipeline matches the fp32 reference bit-for-bit-ish).
// g_Abf[r*HIDDEN+k] = (bf16) A[k][r]   (transposed for coalesced loads)
// g_Bbf[r*HIDDEN+c] = (bf16) B[r][c]
__device__ __align__(16) __nv_bfloat16 g_Abf[RANK * HIDDEN];
__device__ __align__(16) __nv_bfloat16 g_Bbf[RANK * HIDDEN];

// --- storage-format probe (validated R4+) ---
__device__ __forceinline__ int detect_mode(const void* p) {
    const unsigned* w = (const unsigned*)p;
    int vi = 0, vf = 0;
    #pragma unroll
    for (int i = 0; i < 32; i++) {
        unsigned u = w[i];
        int s = (int)u;
        if (s >= -127 && s <= 127) vi++;
        unsigned exp = (u >> 23) & 0xffu;
        if ((u & 0x7fffffffu) == 0u || (exp >= 127u && exp <= 133u)) vf++;
    }
    if (vi >= 24) return 1;
    if (vf >= 24) return 0;
    return 2;
}
__device__ __forceinline__ float load_elem(const void* p, int mode, int i) {
    if (mode == 1) return (float)((const int*)p)[i];
    if (mode == 0) return ((const float*)p)[i];
    return (float)((const signed char*)p)[i];
}

__global__ void prep_kernel(const void* __restrict__ A, const void* __restrict__ B)
{
    __shared__ int mA, mB;
    if (threadIdx.x == 0) { mA = detect_mode(A); mB = detect_mode(B); }
    __syncthreads();
    const int i = blockIdx.x * blockDim.x + threadIdx.x;    // 65536 threads
    {
        const int k = i >> 4, r = i & 15;
        g_Abf[(size_t)r * HIDDEN + k] = __float2bfloat16(load_elem(A, mA, i));
    }
    g_Bbf[i] = __float2bfloat16(load_elem(B, mB, i));
}

// Unpack 8 bf16 (in a float4) to 8 exact f32 via bit ops (2 LOP / pair).
__device__ __forceinline__ void bf8_to_f32(float4 v, float* o) {
    const unsigned w0 = __float_as_uint(v.x), w1 = __float_as_uint(v.y);
    const unsigned w2 = __float_as_uint(v.z), w3 = __float_as_uint(v.w);
    o[0] = __uint_as_float(w0 << 16); o[1] = __uint_as_float(w0 & 0xFFFF0000u);
    o[2] = __uint_as_float(w1 << 16); o[3] = __uint_as_float(w1 & 0xFFFF0000u);
    o[4] = __uint_as_float(w2 << 16); o[5] = __uint_as_float(w2 & 0xFFFF0000u);
    o[6] = __uint_as_float(w3 << 16); o[7] = __uint_as_float(w3 & 0xFFFF0000u);
}

// sin(t): exact identity sin(t) = (-1)^q sin(t - q*pi); Cody-Waite 2-term pi;
// degree-9 odd minimax polynomial on |r| <= pi/2 (FMA pipe only).
__device__ __forceinline__ float fast_sin(float t) {
    const int qi = __float2int_rn(t * 0.3183098861837907f);
    const float q = (float)qi;
    float r = fmaf(q, -3.14159274101257f, t);
    r = fmaf(q, 8.742277657e-8f, r);
    r = (qi & 1) ? -r : r;
    const float s = r * r;
    float p = 2.86567956e-6f;
    p = fmaf(p, s, -1.98559923e-4f);
    p = fmaf(p, s,  8.33338592e-3f);
    p = fmaf(p, s, -1.66666672e-1f);
    return fmaf(p, r * s, r);
}

__global__ __launch_bounds__(THREADS, 2)          // 2 CTAs/SM (R10 config)
void pilora_kernel(const float* __restrict__ x,
                   const float* __restrict__ sA,
                   const float* __restrict__ sB,
                   float* __restrict__ y)
{
    extern __shared__ float xs[];                 // [ROWS][HIDDEN]  64 KB
    __shared__ float red[NWARP][ROWS * RANK];
    __shared__ float hs[ROWS * RANK];

    const int tid  = threadIdx.x;
    const int lane = tid & 31;
    const int w    = tid >> 5;
    const size_t rowbase = (size_t)blockIdx.x * ROWS;

    // ---- stage x tile (coalesced float4) ----
    {
        const float4* xg4 = (const float4*)(x + rowbase * HIDDEN);
        float4* xs4 = (float4*)xs;
        #pragma unroll
        for (int i = 0; i < (ROWS * HIDDEN / 4) / THREADS; i++)
            xs4[tid + i * THREADS] = xg4[tid + i * THREADS];
    }
    __syncthreads();

    // ---- phase 1: h[row][r] = sum_k x[row][k] * A_int[k][r] ----
    // 8 consecutive k per thread per iter; A loaded as 8 bf16 per LDG.128.
    float acc[ROWS][RANK];
    #pragma unroll
    for (int rr = 0; rr < ROWS; rr++)
        #pragma unroll
        for (int r = 0; r < RANK; r++)
            acc[rr][r] = 0.0f;

    #pragma unroll
    for (int i = 0; i < 2; i++) {
        const int k0 = i * 2048 + w * 256 + lane * 8;

        float xv[ROWS][8];
        #pragma unroll
        for (int rr = 0; rr < ROWS; rr++) {
            const float4 xa = *(const float4*)(xs + rr * HIDDEN + k0);
            const float4 xb = *(const float4*)(xs + rr * HIDDEN + k0 + 4);
            xv[rr][0] = xa.x; xv[rr][1] = xa.y; xv[rr][2] = xa.z; xv[rr][3] = xa.w;
            xv[rr][4] = xb.x; xv[rr][5] = xb.y; xv[rr][6] = xb.z; xv[rr][7] = xb.w;
        }

        #pragma unroll
        for (int r = 0; r < RANK; r++) {
            const float4 araw = *(const float4*)(g_Abf + (size_t)r * HIDDEN + k0);
            float av[8];
            bf8_to_f32(araw, av);
            #pragma unroll
            for (int rr = 0; rr < ROWS; rr++) {
                float t = acc[rr][r];
                #pragma unroll
                for (int j = 0; j < 8; j++)
                    t = fmaf(xv[rr][j], av[j], t);
                acc[rr][r] = t;
            }
        }
    }

    // warp butterfly reduction; lane 0 stores per-warp partials
    #pragma unroll
    for (int rr = 0; rr < ROWS; rr++) {
        #pragma unroll
        for (int r = 0; r < RANK; r++) {
            float v = acc[rr][r];
            v += __shfl_xor_sync(0xffffffffu, v, 16);
            v += __shfl_xor_sync(0xffffffffu, v, 8);
            v += __shfl_xor_sync(0xffffffffu, v, 4);
            v += __shfl_xor_sync(0xffffffffu, v, 2);
            v += __shfl_xor_sync(0xffffffffu, v, 1);
            if (lane == 0) red[w][rr * RANK + r] = v;
        }
    }
    __syncthreads();

    if (tid < ROWS * RANK) {
        float h = 0.0f;
        #pragma unroll
        for (int ww = 0; ww < NWARP; ww++) h += red[ww][tid];
        hs[tid] = h * sA[tid & (RANK - 1)] * TWO_OVER_PI;   // exact fp32 scaling
    }
    __syncthreads();

    // ---- phase 2: y = x + 2*sin( (sum_r hs*B_int[r][c]) * sB[c] ) ----
    #pragma unroll
    for (int i = 0; i < 2; i++) {
        const int c0 = i * 2048 + w * 256 + lane * 8;

        float acc2[ROWS][8];
        #pragma unroll
        for (int rr = 0; rr < ROWS; rr++)
            #pragma unroll
            for (int j = 0; j < 8; j++)
                acc2[rr][j] = 0.0f;

        #pragma unroll
        for (int r = 0; r < RANK; r++) {
            const float4 braw = *(const float4*)(g_Bbf + (size_t)r * HIDDEN + c0);
            float b[8];
            bf8_to_f32(braw, b);
            #pragma unroll
            for (int rr = 0; rr < ROWS; rr++) {
                const float hr = hs[rr * RANK + r];   // conflict-free broadcast
                #pragma unroll
                for (int j = 0; j < 8; j++)
                    acc2[rr][j] = fmaf(hr, b[j], acc2[rr][j]);
            }
        }

        // per-column output scale, then sin epilogue
        float sb[8];
        {
            const float4 s0 = *(const float4*)(sB + c0);
            const float4 s1 = *(const float4*)(sB + c0 + 4);
            sb[0] = s0.x; sb[1] = s0.y; sb[2] = s0.z; sb[3] = s0.w;
            sb[4] = s1.x; sb[5] = s1.y; sb[6] = s1.z; sb[7] = s1.w;
        }

        #pragma unroll
        for (int rr = 0; rr < ROWS; rr++) {
            const float4 xa = *(const float4*)(xs + rr * HIDDEN + c0);
            const float4 xb = *(const float4*)(xs + rr * HIDDEN + c0 + 4);
            const float xr[8] = {xa.x, xa.y, xa.z, xa.w, xb.x, xb.y, xb.z, xb.w};
            float o[8];
            #pragma unroll
            for (int j = 0; j < 8; j++)
                o[j] = fmaf(2.0f, fast_sin(acc2[rr][j] * sb[j]), xr[j]);
            float4 o0, o1;
            o0.x = o[0]; o0.y = o[1]; o0.z = o[2]; o0.w = o[3];
            o1.x = o[4]; o1.y = o[5]; o1.z = o[6]; o1.w = o[7];
            float* yp = y + (rowbase + rr) * HIDDEN + c0;
            *(float4*)(yp)     = o0;
            *(float4*)(yp + 4) = o1;
        }
    }
}

extern "C" void kernel_launch(void* const* d_in, const int* in_sizes, int n_in,
                              void* d_out, int out_size)
{
    // Rank-order binding by size (robust; validated since R4)
    int idx[16];
    const int m = (n_in < 16) ? n_in : 16;
    for (int i = 0; i < m; i++) idx[i] = i;
    for (int i = 0; i < m; i++) {
        int best = i;
        for (int j = i + 1; j < m; j++)
            if (in_sizes[idx[j]] < in_sizes[idx[best]]) best = j;
        if (best != i) {
            int t = idx[best];
            for (int j = best; j > i; j--) idx[j] = idx[j - 1];
            idx[i] = t;
        }
    }
    const float* sA = (const float*)d_in[idx[0]];
    const float* sB = (const float*)d_in[idx[1]];
    const void*  A  = d_in[idx[2]];
    const void*  B  = d_in[idx[3]];
    const float* x  = (const float*)d_in[idx[m - 1]];
    float* y = (float*)d_out;

    prep_kernel<<<(HIDDEN * RANK) / 256, 256>>>(A, B);

    const size_t smem = (size_t)ROWS * HIDDEN * sizeof(float);   // 64 KB
    cudaFuncSetAttribute(pilora_kernel,
                         cudaFuncAttributeMaxDynamicSharedMemorySize, (int)smem);
    pilora_kernel<<<TOTAL_ROWS / ROWS, THREADS, smem>>>(x, sA, sB, y);
}

// round 13
// speedup vs baseline: 1.0987x; 1.0681x over previous
#include <cuda_runtime.h>
#include <cstdint>

#define HIDDEN  4096
#define RANK    16
#define ROWS    4
#define THREADS 256
#define NWARP   8
#define TOTAL_ROWS 16384
#define TWO_OVER_PI 0.63661977236758134f

// Dequantized weights in device scratch (no allocations).
// g_Aft[r*HIDDEN+k] = A[k][r] * sA[r] * 2/pi   (transposed, coalesced loads)
// g_Bf [r*HIDDEN+c] = B[r][c] * sB[c]
__device__ float g_Aft[RANK * HIDDEN];
__device__ float g_Bf[RANK * HIDDEN];

// --- storage-format probe (validated R4+) ---
__device__ __forceinline__ int detect_mode(const void* p) {
    const unsigned* w = (const unsigned*)p;
    int vi = 0, vf = 0;
    #pragma unroll
    for (int i = 0; i < 32; i++) {
        unsigned u = w[i];
        int s = (int)u;
        if (s >= -127 && s <= 127) vi++;
        unsigned exp = (u >> 23) & 0xffu;
        if ((u & 0x7fffffffu) == 0u || (exp >= 127u && exp <= 133u)) vf++;
    }
    if (vi >= 24) return 1;
    if (vf >= 24) return 0;
    return 2;
}
__device__ __forceinline__ float load_elem(const void* p, int mode, int i) {
    if (mode == 1) return (float)((const int*)p)[i];
    if (mode == 0) return ((const float*)p)[i];
    return (float)((const signed char*)p)[i];
}

__global__ void prep_kernel(const void* __restrict__ A, const void* __restrict__ B,
                            const float* __restrict__ sA, const float* __restrict__ sB)
{
    __shared__ int mA, mB;
    if (threadIdx.x == 0) { mA = detect_mode(A); mB = detect_mode(B); }
    __syncthreads();
    const int i = blockIdx.x * blockDim.x + threadIdx.x;    // 65536 threads
    {
        const int k = i >> 4, r = i & 15;
        g_Aft[(size_t)r * HIDDEN + k] = load_elem(A, mA, i) * sA[r] * TWO_OVER_PI;
    }
    g_Bf[i] = load_elem(B, mB, i) * sB[i & (HIDDEN - 1)];
}

// sin(t): exact identity sin(t) = (-1)^q sin(t - q*pi); Cody-Waite 2-term pi;
// degree-9 odd minimax polynomial on |r| <= pi/2 (FMA pipe only).
__device__ __forceinline__ float fast_sin(float t) {
    const int qi = __float2int_rn(t * 0.3183098861837907f);
    const float q = (float)qi;
    float r = fmaf(q, -3.14159274101257f, t);
    r = fmaf(q, 8.742277657e-8f, r);
    r = (qi & 1) ? -r : r;
    const float s = r * r;
    float p = 2.86567956e-6f;
    p = fmaf(p, s, -1.98559923e-4f);
    p = fmaf(p, s,  8.33338592e-3f);
    p = fmaf(p, s, -1.66666672e-1f);
    return fmaf(p, r * s, r);
}

__global__ __launch_bounds__(THREADS, 2)          // 2 CTAs/SM
void pilora_kernel(const float* __restrict__ x, float* __restrict__ y)
{
    extern __shared__ float xs[];                 // [ROWS][HIDDEN]  64 KB
    __shared__ float red[NWARP][ROWS * RANK];
    __shared__ float hs[ROWS * RANK];

    const int tid  = threadIdx.x;
    const int lane = tid & 31;
    const int w    = tid >> 5;
    const size_t rowbase = (size_t)blockIdx.x * ROWS;

    // ---- phase 1 (staging fused): load x from GMEM, stash to smem for the
    // phase-2 residual, and FMA against A. Note: warp w's k-range here equals
    // its c-range in phase 2, so the xs stripe is warp-private -> no staging
    // barrier needed (the reduction barriers below cover hs ordering).
    float acc[ROWS][RANK];
    #pragma unroll
    for (int rr = 0; rr < ROWS; rr++)
        #pragma unroll
        for (int r = 0; r < RANK; r++)
            acc[rr][r] = 0.0f;

    #pragma unroll
    for (int i = 0; i < 4; i++) {
        const int k0 = w * 512 + i * 128 + lane * 4;

        float4 xv[ROWS];
        #pragma unroll
        for (int rr = 0; rr < ROWS; rr++) {
            xv[rr] = *(const float4*)(x + (rowbase + rr) * HIDDEN + k0);
            *(float4*)(xs + rr * HIDDEN + k0) = xv[rr];
        }

        // rank-chunked A loads: 4 independent LDG.128 in flight, then 64 FMAs
        #pragma unroll
        for (int rc = 0; rc < 4; rc++) {
            float4 av[4];
            #pragma unroll
            for (int c = 0; c < 4; c++)
                av[c] = *(const float4*)(g_Aft + (size_t)(rc * 4 + c) * HIDDEN + k0);
            #pragma unroll
            for (int c = 0; c < 4; c++) {
                const int r = rc * 4 + c;
                #pragma unroll
                for (int rr = 0; rr < ROWS; rr++) {
                    float t = acc[rr][r];
                    t = fmaf(xv[rr].x, av[c].x, t);
                    t = fmaf(xv[rr].y, av[c].y, t);
                    t = fmaf(xv[rr].z, av[c].z, t);
                    t = fmaf(xv[rr].w, av[c].w, t);
                    acc[rr][r] = t;
                }
            }
        }
    }

    // warp butterfly reduction; lane 0 stores per-warp partials
    #pragma unroll
    for (int rr = 0; rr < ROWS; rr++) {
        #pragma unroll
        for (int r = 0; r < RANK; r++) {
            float v = acc[rr][r];
            v += __shfl_xor_sync(0xffffffffu, v, 16);
            v += __shfl_xor_sync(0xffffffffu, v, 8);
            v += __shfl_xor_sync(0xffffffffu, v, 4);
            v += __shfl_xor_sync(0xffffffffu, v, 2);
            v += __shfl_xor_sync(0xffffffffu, v, 1);
            if (lane == 0) red[w][rr * RANK + r] = v;
        }
    }
    __syncthreads();

    if (tid < ROWS * RANK) {
        float h = 0.0f;
        #pragma unroll
        for (int ww = 0; ww < NWARP; ww++) h += red[ww][tid];
        hs[tid] = h;                       // sA and 2/pi already folded into Aft
    }
    __syncthreads();

    // ---- phase 2: y = x + 2*sin( sum_r hs[row][r] * Bf[r][c] ) ----
    #pragma unroll
    for (int i = 0; i < 4; i++) {
        const int c0 = w * 512 + i * 128 + lane * 4;

        float acc2[ROWS][4];
        #pragma unroll
        for (int rr = 0; rr < ROWS; rr++)
            #pragma unroll
            for (int j = 0; j < 4; j++)
                acc2[rr][j] = 0.0f;

        // rank-chunked B loads: 4 independent LDG.128, then 64 FMAs
        #pragma unroll
        for (int rc = 0; rc < 4; rc++) {
            float4 bv[4];
            #pragma unroll
            for (int c = 0; c < 4; c++)
                bv[c] = *(const float4*)(g_Bf + (size_t)(rc * 4 + c) * HIDDEN + c0);
            #pragma unroll
            for (int c = 0; c < 4; c++) {
                const int r = rc * 4 + c;
                #pragma unroll
                for (int rr = 0; rr < ROWS; rr++) {
                    const float hr = hs[rr * RANK + r];   // conflict-free broadcast
                    acc2[rr][0] = fmaf(hr, bv[c].x, acc2[rr][0]);
                    acc2[rr][1] = fmaf(hr, bv[c].y, acc2[rr][1]);
                    acc2[rr][2] = fmaf(hr, bv[c].z, acc2[rr][2]);
                    acc2[rr][3] = fmaf(hr, bv[c].w, acc2[rr][3]);
                }
            }
        }

        #pragma unroll
        for (int rr = 0; rr < ROWS; rr++) {
            const float4 xv = *(const float4*)(xs + rr * HIDDEN + c0);
            float4 ov;
            ov.x = fmaf(2.0f, fast_sin(acc2[rr][0]), xv.x);
            ov.y = fmaf(2.0f, fast_sin(acc2[rr][1]), xv.y);
            ov.z = fmaf(2.0f, fast_sin(acc2[rr][2]), xv.z);
            ov.w = fmaf(2.0f, fast_sin(acc2[rr][3]), xv.w);
            *(float4*)(y + (rowbase + rr) * HIDDEN + c0) = ov;
        }
    }
}

extern "C" void kernel_launch(void* const* d_in, const int* in_sizes, int n_in,
                              void* d_out, int out_size)
{
    // Rank-order binding by size (robust; validated since R4)
    int idx[16];
    const int m = (n_in < 16) ? n_in : 16;
    for (int i = 0; i < m; i++) idx[i] = i;
    for (int i = 0; i < m; i++) {
        int best = i;
        for (int j = i + 1; j < m; j++)
            if (in_sizes[idx[j]] < in_sizes[idx[best]]) best = j;
        if (best != i) {
            int t = idx[best];
            for (int j = best; j > i; j--) idx[j] = idx[j - 1];
            idx[i] = t;
        }
    }
    const float* sA = (const float*)d_in[idx[0]];
    const float* sB = (const float*)d_in[idx[1]];
    const void*  A  = d_in[idx[2]];
    const void*  B  = d_in[idx[3]];
    const float* x  = (const float*)d_in[idx[m - 1]];
    float* y = (float*)d_out;

    prep_kernel<<<(HIDDEN * RANK) / 256, 256>>>(A, B, sA, sB);

    const size_t smem = (size_t)ROWS * HIDDEN * sizeof(float);   // 64 KB
    cudaFuncSetAttribute(pilora_kernel,
                         cudaFuncAttributeMaxDynamicSharedMemorySize, (int)smem);
    pilora_kernel<<<TOTAL_ROWS / ROWS, THREADS, smem>>>(x, y);
}